// round 1
// baseline (speedup 1.0000x reference)
#include <cuda_runtime.h>
#include <cuda_bf16.h>
#include <cstdint>
#include <cstddef>

// ---------------------------------------------------------------------------
// BiLSTM: T=1024, B=32, D_IN=256, H=256, L=3, 3-gate cell, highway on l>0.
//
// Structure per layer l:
//   zx = input @ Wx + b        (big GEMM, time-parallel)   -> g_zxf / g_zxb
//   recurrent scan (fwd+bwd simultaneously, persistent kernel, grid barrier)
//   highway (l>0): g = sigmoid(raw @ W_hw + b_hw); out = g*raw + (1-g)*prev
// ---------------------------------------------------------------------------

#define T_LEN 1024
#define BATCH 32
#define HID   256
#define ZN    768              // 3*H
#define MROWS (T_LEN*BATCH)    // 32768

// ------------------------- device scratch (no cudaMalloc allowed) ----------
__device__ float g_zxf[(size_t)MROWS * ZN];   // 96 MB
__device__ float g_zxb[(size_t)MROWS * ZN];   // 96 MB  (also works: ghw scratch fits in g_zxf)
__device__ float g_buf0[(size_t)MROWS * 512]; // 64 MB
__device__ float g_buf1[(size_t)MROWS * 512]; // 64 MB
__device__ float g_h[2][2][HID * BATCH];      // [dir][pingpong][k*32+b]
__device__ volatile unsigned g_barcnt[2];
__device__ volatile unsigned g_bargen[2];

__device__ __forceinline__ float sigm(float x) { return 1.f / (1.f + __expf(-x)); }

// ------------------------- SGEMM: C[M,N] = A[M,K] @ B[K,N] + bias[N] -------
// BM=128 BN=64 BK=16, 256 threads, 8x4 per thread.
#define BM 128
#define BN 64
#define BK 16

__global__ __launch_bounds__(256) void sgemm_bias(
    const float* __restrict__ A, const float* __restrict__ B,
    const float* __restrict__ bias, float* __restrict__ C,
    int M, int N, int K)
{
    __shared__ float As[BK][BM];   // transposed A tile
    __shared__ float Bs[BK][BN];

    const int bm = blockIdx.y * BM;
    const int bn = blockIdx.x * BN;
    const int tid = threadIdx.x;
    const int tx = tid & 15;       // n: 16 groups * 4
    const int ty = tid >> 4;       // m: 16 groups * 8

    float acc[8][4];
#pragma unroll
    for (int i = 0; i < 8; i++)
#pragma unroll
        for (int jj = 0; jj < 4; jj++) acc[i][jj] = 0.f;

    for (int k0 = 0; k0 < K; k0 += BK) {
        // A tile: 128 rows x 16 cols = 512 float4, 2 per thread
#pragma unroll
        for (int i = 0; i < 2; i++) {
            int f = tid + i * 256;
            int r = f >> 2, c4 = f & 3;
            float4 v = *(const float4*)(A + (size_t)(bm + r) * K + k0 + c4 * 4);
            As[c4 * 4 + 0][r] = v.x;
            As[c4 * 4 + 1][r] = v.y;
            As[c4 * 4 + 2][r] = v.z;
            As[c4 * 4 + 3][r] = v.w;
        }
        // B tile: 16 rows x 64 cols = 256 float4, 1 per thread
        {
            int r = tid >> 4, c4 = tid & 15;
            float4 v = *(const float4*)(B + (size_t)(k0 + r) * N + bn + c4 * 4);
            *(float4*)&Bs[r][c4 * 4] = v;
        }
        __syncthreads();
#pragma unroll
        for (int k = 0; k < BK; k++) {
            float a[8], b[4];
            *(float4*)(a)     = *(const float4*)&As[k][ty * 8];
            *(float4*)(a + 4) = *(const float4*)&As[k][ty * 8 + 4];
            *(float4*)(b)     = *(const float4*)&Bs[k][tx * 4];
#pragma unroll
            for (int i = 0; i < 8; i++)
#pragma unroll
                for (int jj = 0; jj < 4; jj++) acc[i][jj] += a[i] * b[jj];
        }
        __syncthreads();
    }
    float4 bb = *(const float4*)(bias + bn + tx * 4);
#pragma unroll
    for (int i = 0; i < 8; i++) {
        int row = bm + ty * 8 + i;
        float4 o;
        o.x = acc[i][0] + bb.x;
        o.y = acc[i][1] + bb.y;
        o.z = acc[i][2] + bb.z;
        o.w = acc[i][3] + bb.w;
        *(float4*)(C + (size_t)row * N + bn + tx * 4) = o;
    }
}

// ------------------------- recurrent scan kernel ---------------------------
// 128 blocks: blocks [0,64) forward scan, [64,128) backward scan.
// Each block owns 4 h-columns (=> 12 z-columns). 384 threads.
#define NSCAN 64
#define RTH   384

__device__ __forceinline__ void scan_barrier(int s, unsigned nb)
{
    __syncthreads();
    if (threadIdx.x == 0) {
        unsigned g = g_bargen[s];
        __threadfence();
        unsigned a = atomicAdd((unsigned*)&g_barcnt[s], 1u);
        if (a == nb - 1) {
            g_barcnt[s] = 0;
            __threadfence();
            g_bargen[s] = g + 1;
        } else {
            while (g_bargen[s] == g) { }
            __threadfence();
        }
    }
    __syncthreads();
}

__global__ __launch_bounds__(RTH) void recur_kernel(
    const float* __restrict__ Whf, const float* __restrict__ Whb,
    const float* __restrict__ h0, const float* __restrict__ c0,
    float* __restrict__ y, float* __restrict__ hn, float* __restrict__ cn,
    int layer)
{
    const int dir = blockIdx.x / NSCAN;          // 0 = fwd, 1 = bwd
    const int sb  = blockIdx.x % NSCAN;
    const float* Wh = dir ? Whb : Whf;
    const float* zx = dir ? g_zxb : g_zxf;

    const int c0col = sb * 4;
    const int tid = threadIdx.x;
    const int j   = tid >> 5;      // 0..11 : z-column within slice
    const int b   = tid & 31;      // batch
    const int gate = j >> 2;       // 0=i 1=j 2=o
    const int lc   = j & 3;        // local h column
    const int zcol = gate * 256 + c0col + lc;

    __shared__ float Ws[12][256];      // Wh columns, [j][k]
    __shared__ float hs[256][32];      // h, [k][b]
    __shared__ float zres[12][32];
    __shared__ float cs[4][32];

    // load weight slice
    for (int k = b; k < 256; k += 32)
        Ws[j][k] = Wh[(size_t)k * ZN + zcol];

    // init c-state and h buffer slice
    if (tid < 128) {
        int lc2 = tid >> 5, b2 = tid & 31;
        cs[lc2][b2] = c0[c0col + lc2];
        g_h[dir][0][(c0col + lc2) * 32 + b2] = h0[c0col + lc2];
    }
    scan_barrier(dir, NSCAN);

    for (int tt = 0; tt < T_LEN; tt++) {
        const int t = dir ? (T_LEN - 1 - tt) : tt;

        // broadcast h into smem (bypass L1: written by other SMs last step)
        {
            const float4* src = (const float4*)g_h[dir][tt & 1];
            float4* dst = (float4*)hs;
            for (int i = tid; i < (HID * BATCH) / 4; i += RTH)
                dst[i] = __ldcg(src + i);
        }
        const float xz = __ldg(&zx[(size_t)t * (BATCH * ZN) + b * ZN + zcol]);
        __syncthreads();

        // dot: z[j][b] = sum_k hs[k][b] * Ws[j][k]
        float a0 = 0.f, a1 = 0.f, a2 = 0.f, a3 = 0.f;
#pragma unroll
        for (int k = 0; k < 256; k += 4) {
            float4 w = *(const float4*)&Ws[j][k];
            a0 += hs[k + 0][b] * w.x;
            a1 += hs[k + 1][b] * w.y;
            a2 += hs[k + 2][b] * w.z;
            a3 += hs[k + 3][b] * w.w;
        }
        zres[j][b] = (a0 + a1) + (a2 + a3) + xz;
        __syncthreads();

        if (tid < 128) {
            int lc2 = tid >> 5, b2 = tid & 31;
            float iv = zres[lc2][b2];
            float jv = zres[4 + lc2][b2];
            float ov = zres[8 + lc2][b2];
            float ig = sigm(iv);
            float c  = cs[lc2][b2];
            float nc = (1.f - ig) * c + ig * tanhf(jv);
            cs[lc2][b2] = nc;
            float nh = tanhf(nc) * sigm(ov);
            g_h[dir][(tt + 1) & 1][(c0col + lc2) * 32 + b2] = nh;
            y[(size_t)t * (BATCH * 512) + b2 * 512 + dir * 256 + c0col + lc2] = nh;
            if (tt == T_LEN - 1) {
                int si = 2 * layer + dir;
                hn[(size_t)si * (BATCH * HID) + b2 * HID + c0col + lc2] = nh;
                cn[(size_t)si * (BATCH * HID) + b2 * HID + c0col + lc2] = nc;
            }
        }
        scan_barrier(dir, NSCAN);
    }
}

// ------------------------- highway elementwise -----------------------------
__global__ __launch_bounds__(256) void highway_ew(
    const float4* __restrict__ gz, const float4* __restrict__ raw,
    const float4* __restrict__ prev, float4* __restrict__ dst, int n4)
{
    int i = blockIdx.x * blockDim.x + threadIdx.x;
    if (i < n4) {
        float4 G = gz[i], R = raw[i], P = prev[i], o;
        float s;
        s = sigm(G.x); o.x = s * R.x + (1.f - s) * P.x;
        s = sigm(G.y); o.y = s * R.y + (1.f - s) * P.y;
        s = sigm(G.z); o.z = s * R.z + (1.f - s) * P.z;
        s = sigm(G.w); o.w = s * R.w + (1.f - s) * P.w;
        dst[i] = o;
    }
}

// ------------------------- host launcher -----------------------------------
extern "C" void kernel_launch(void* const* d_in, const int* in_sizes, int n_in,
                              void* d_out, int out_size)
{
    (void)in_sizes; (void)n_in; (void)out_size;

    const float* x    = (const float*)d_in[0];
    const float* h0   = (const float*)d_in[1];
    const float* c0   = (const float*)d_in[2];
    const float* Wf0  = (const float*)d_in[3];
    const float* bf0  = (const float*)d_in[4];
    const float* Wb0  = (const float*)d_in[5];
    const float* bb0  = (const float*)d_in[6];
    const float* Wf1  = (const float*)d_in[7];
    const float* bf1  = (const float*)d_in[8];
    const float* Wb1  = (const float*)d_in[9];
    const float* bb1  = (const float*)d_in[10];
    const float* Wf2  = (const float*)d_in[11];
    const float* bf2  = (const float*)d_in[12];
    const float* Wb2  = (const float*)d_in[13];
    const float* bb2  = (const float*)d_in[14];
    const float* W_hw = (const float*)d_in[15];
    const float* b_hw = (const float*)d_in[16];

    float* out = (float*)d_out;                       // [1024,32,512]
    float* hn  = out + (size_t)MROWS * 512;           // [6,32,256]
    float* cn  = hn + 6 * BATCH * HID;                // [6,32,256]

    float *zxf, *zxb, *buf0, *buf1;
    cudaGetSymbolAddress((void**)&zxf,  g_zxf);
    cudaGetSymbolAddress((void**)&zxb,  g_zxb);
    cudaGetSymbolAddress((void**)&buf0, g_buf0);
    cudaGetSymbolAddress((void**)&buf1, g_buf1);

    const dim3 g768(ZN / BN, MROWS / BM);   // (12, 256)
    const dim3 g512(512 / BN, MROWS / BM);  // (8, 256)
    const int n4 = (MROWS * 512) / 4;
    const int ewb = (n4 + 255) / 256;

    // ---- layer 0 ----
    sgemm_bias<<<g768, 256>>>(x, Wf0, bf0, zxf, MROWS, ZN, 256);
    sgemm_bias<<<g768, 256>>>(x, Wb0, bb0, zxb, MROWS, ZN, 256);
    recur_kernel<<<2 * NSCAN, RTH>>>(Wf0 + (size_t)256 * ZN, Wb0 + (size_t)256 * ZN,
                                     h0, c0, buf0, hn, cn, 0);
    // ---- layer 1 ----
    sgemm_bias<<<g768, 256>>>(buf0, Wf1, bf1, zxf, MROWS, ZN, 512);
    sgemm_bias<<<g768, 256>>>(buf0, Wb1, bb1, zxb, MROWS, ZN, 512);
    recur_kernel<<<2 * NSCAN, RTH>>>(Wf1 + (size_t)512 * ZN, Wb1 + (size_t)512 * ZN,
                                     h0, c0, buf1, hn, cn, 1);
    sgemm_bias<<<g512, 256>>>(buf1, W_hw, b_hw, zxf, MROWS, 512, 512);   // gate logits -> scratch
    highway_ew<<<ewb, 256>>>((const float4*)zxf, (const float4*)buf1,
                             (const float4*)buf0, (float4*)buf1, n4);
    // ---- layer 2 ----
    sgemm_bias<<<g768, 256>>>(buf1, Wf2, bf2, zxf, MROWS, ZN, 512);
    sgemm_bias<<<g768, 256>>>(buf1, Wb2, bb2, zxb, MROWS, ZN, 512);
    recur_kernel<<<2 * NSCAN, RTH>>>(Wf2 + (size_t)512 * ZN, Wb2 + (size_t)512 * ZN,
                                     h0, c0, buf0, hn, cn, 2);
    sgemm_bias<<<g512, 256>>>(buf0, W_hw, b_hw, zxf, MROWS, 512, 512);
    highway_ew<<<ewb, 256>>>((const float4*)zxf, (const float4*)buf0,
                             (const float4*)buf1, (float4*)out, n4);
}

// round 2
// speedup vs baseline: 1.4626x; 1.4626x over previous
#include <cuda_runtime.h>
#include <cstdint>
#include <cstddef>

// ---------------------------------------------------------------------------
// BiLSTM T=1024 B=32 H=256 L=3, 3-gate cell, highway on l>0.
//   zx GEMMs (time-parallel, FFMA2 SGEMM)
//   recurrence: 16 clusters x 8 CTAs; cluster = (dir, 4-batch group).
//     Each CTA: 96 z-cols (32 h-cols x 3 gates) x 4 batches, Wh slice in SMEM,
//     h exchanged via DSMEM (st.shared::cluster), barrier.cluster per step.
// ---------------------------------------------------------------------------

#define T_LEN 1024
#define BATCH 32
#define ZN    768
#define MROWS (T_LEN*BATCH)

__device__ float g_zxf[(size_t)MROWS * ZN];
__device__ float g_zxb[(size_t)MROWS * ZN];
__device__ float g_buf0[(size_t)MROWS * 512];
__device__ float g_buf1[(size_t)MROWS * 512];

__device__ __forceinline__ float sigm(float x) { return 1.f / (1.f + __expf(-x)); }

// ---- f32x2 packed helpers --------------------------------------------------
__device__ __forceinline__ unsigned long long pack2(float lo, float hi) {
    unsigned long long r;
    asm("mov.b64 %0, {%1, %2};" : "=l"(r) : "f"(lo), "f"(hi));
    return r;
}
__device__ __forceinline__ void unpack2(unsigned long long v, float& lo, float& hi) {
    asm("mov.b64 {%0, %1}, %2;" : "=f"(lo), "=f"(hi) : "l"(v));
}
__device__ __forceinline__ void ffma2(unsigned long long& d, unsigned long long a, unsigned long long b) {
    asm("fma.rn.f32x2 %0, %1, %2, %3;" : "=l"(d) : "l"(a), "l"(b), "l"(d));
}
__device__ __forceinline__ unsigned smaddr(const void* p) {
    unsigned a;
    asm("{ .reg .u64 t; cvta.to.shared.u64 t, %1; cvt.u32.u64 %0, t; }" : "=r"(a) : "l"(p));
    return a;
}
__device__ __forceinline__ void st_cluster_f32(unsigned addr, unsigned rank, float v) {
    asm volatile("{ .reg .b32 ra; mapa.shared::cluster.u32 ra, %0, %1; st.shared::cluster.f32 [ra], %2; }"
                 :: "r"(addr), "r"(rank), "f"(v) : "memory");
}
#define CLUSTER_SYNC() do { \
    asm volatile("barrier.cluster.arrive.aligned;" ::: "memory"); \
    asm volatile("barrier.cluster.wait.aligned;" ::: "memory"); \
} while (0)

// ------------------------- SGEMM (FFMA2): C = A@B + bias -------------------
#define BM 128
#define BN 64
#define BK 16

__global__ __launch_bounds__(256) void sgemm_bias(
    const float* __restrict__ A, const float* __restrict__ B,
    const float* __restrict__ bias, float* __restrict__ C,
    int M, int N, int K)
{
    __shared__ float As[BK][BM];
    __shared__ float Bs[BK][BN];

    const int bm = blockIdx.y * BM;
    const int bn = blockIdx.x * BN;
    const int tid = threadIdx.x;
    const int tx = tid & 15;
    const int ty = tid >> 4;

    unsigned long long acc2[4][4];   // [m-pair][n], each = 2 rows
#pragma unroll
    for (int p = 0; p < 4; p++)
#pragma unroll
        for (int j = 0; j < 4; j++) acc2[p][j] = 0ull;

    for (int k0 = 0; k0 < K; k0 += BK) {
#pragma unroll
        for (int i = 0; i < 2; i++) {
            int f = tid + i * 256;
            int r = f >> 2, c4 = f & 3;
            float4 v = *(const float4*)(A + (size_t)(bm + r) * K + k0 + c4 * 4);
            As[c4 * 4 + 0][r] = v.x;
            As[c4 * 4 + 1][r] = v.y;
            As[c4 * 4 + 2][r] = v.z;
            As[c4 * 4 + 3][r] = v.w;
        }
        {
            int r = tid >> 4, c4 = tid & 15;
            *(float4*)&Bs[r][c4 * 4] = *(const float4*)(B + (size_t)(k0 + r) * N + bn + c4 * 4);
        }
        __syncthreads();
#pragma unroll
        for (int k = 0; k < BK; k++) {
            ulonglong2 A0 = *(const ulonglong2*)&As[k][ty * 8];
            ulonglong2 A1 = *(const ulonglong2*)&As[k][ty * 8 + 4];
            float4 bv = *(const float4*)&Bs[k][tx * 4];
            unsigned long long bb0 = pack2(bv.x, bv.x);
            unsigned long long bb1 = pack2(bv.y, bv.y);
            unsigned long long bb2 = pack2(bv.z, bv.z);
            unsigned long long bb3 = pack2(bv.w, bv.w);
            ffma2(acc2[0][0], A0.x, bb0); ffma2(acc2[1][0], A0.y, bb0);
            ffma2(acc2[2][0], A1.x, bb0); ffma2(acc2[3][0], A1.y, bb0);
            ffma2(acc2[0][1], A0.x, bb1); ffma2(acc2[1][1], A0.y, bb1);
            ffma2(acc2[2][1], A1.x, bb1); ffma2(acc2[3][1], A1.y, bb1);
            ffma2(acc2[0][2], A0.x, bb2); ffma2(acc2[1][2], A0.y, bb2);
            ffma2(acc2[2][2], A1.x, bb2); ffma2(acc2[3][2], A1.y, bb2);
            ffma2(acc2[0][3], A0.x, bb3); ffma2(acc2[1][3], A0.y, bb3);
            ffma2(acc2[2][3], A1.x, bb3); ffma2(acc2[3][3], A1.y, bb3);
        }
        __syncthreads();
    }
    float4 bb = *(const float4*)(bias + bn + tx * 4);
#pragma unroll
    for (int p = 0; p < 4; p++) {
        float lo[4], hi[4];
#pragma unroll
        for (int j = 0; j < 4; j++) unpack2(acc2[p][j], lo[j], hi[j]);
        int row0 = bm + ty * 8 + 2 * p;
        float4 o0, o1;
        o0.x = lo[0] + bb.x; o0.y = lo[1] + bb.y; o0.z = lo[2] + bb.z; o0.w = lo[3] + bb.w;
        o1.x = hi[0] + bb.x; o1.y = hi[1] + bb.y; o1.z = hi[2] + bb.z; o1.w = hi[3] + bb.w;
        *(float4*)(C + (size_t)row0 * N + bn + tx * 4)       = o0;
        *(float4*)(C + (size_t)(row0 + 1) * N + bn + tx * 4) = o1;
    }
}

// ------------------------- recurrent scan (clustered) ----------------------
// grid = 128 CTAs, cluster size 8. cid = blockIdx.x/8; dir = cid>>3; bg = cid&7.
// CTA rank r owns h-cols [r*32, r*32+32) -> z-cols {g*256 + r*32 + lc}.
// 384 threads.
//   dot phase:    thread = (jg = tid%24, kc = tid/24); jg: quad of 4 local j;
//                 kc: 16-wide k-chunk. Conflict-free W LDS.128, broadcast h.
//   reduce/cell:  thread = (rj = tid>>2, rb = tid&3); 16 partials summed + zx.
// SMEM (floats): WS2[24][1028] | HS[2][4][264] | ZP[96][17][4] | ZF[96][5]
#define RC_WS   0
#define RC_HS   24672
#define RC_ZP   26784
#define RC_ZF   33312
#define RC_FLTS 33792
#define RC_BYTES (RC_FLTS * 4)

__global__ void __cluster_dims__(8, 1, 1) __launch_bounds__(384, 1)
recur2(const float* __restrict__ Whf, const float* __restrict__ Whb,
       const float* __restrict__ h0, const float* __restrict__ c0,
       float* __restrict__ y, float* __restrict__ hn, float* __restrict__ cn,
       int layer)
{
    extern __shared__ float sm[];
    float* WS = sm + RC_WS;
    float* HS = sm + RC_HS;
    float* ZP = sm + RC_ZP;
    float* ZF = sm + RC_ZF;

    const int cid = blockIdx.x >> 3;
    const int dir = cid >> 3;
    const int bg  = cid & 7;
    unsigned rank;
    asm("mov.u32 %0, %%cluster_ctarank;" : "=r"(rank));

    const float* Wh = dir ? Whb : Whf;
    const float* zx = dir ? g_zxb : g_zxf;
    const int tid = threadIdx.x;

    const int jg = tid % 24;          // j-quad index
    const int kc = tid / 24;          // k-chunk 0..15
    const int rj = tid >> 2;          // local z-col 0..95
    const int rb = tid & 3;           // local batch
    const int bglob = bg * 4 + rb;
    const int zcolr = (rj >> 5) * 256 + (int)rank * 32 + (rj & 31);

    // ---- load weight slice: WS[jg][k][g4], pitch 1028 floats per jg ----
    for (int it = tid; it < 96 * 256; it += 384) {
        int k = it / 96, j = it % 96;
        int zc = (j >> 5) * 256 + (int)rank * 32 + (j & 31);
        WS[(j >> 2) * 1028 + k * 4 + (j & 3)] = Wh[(size_t)k * ZN + zc];
    }
    // ---- init h buffer 0 (full h0, replicated per batch) ----
    for (int it = tid; it < 4 * 256; it += 384) {
        int b = it >> 8, k = it & 255;
        HS[b * 264 + k] = h0[k];
    }
    float creg = 0.f;
    if (rj < 32) creg = c0[(int)rank * 32 + rj];
    __syncthreads();
    CLUSTER_SYNC();

    const float* wp = WS + jg * 1028 + kc * 64;

    for (int tt = 0; tt < T_LEN; tt++) {
        const int t = dir ? (T_LEN - 1 - tt) : tt;
        const float zxv = __ldg(&zx[((size_t)t * BATCH + bglob) * ZN + zcolr]);

        // ---------------- dot phase ----------------
        const float* hcur = HS + (tt & 1) * 1056 + kc * 16;
        unsigned long long acc[2][4];
#pragma unroll
        for (int g2 = 0; g2 < 2; g2++)
#pragma unroll
            for (int b = 0; b < 4; b++) acc[g2][b] = 0ull;

#pragma unroll
        for (int q = 0; q < 4; q++) {
            float4 h0q = *(const float4*)(hcur + 0 * 264 + q * 4);
            float4 h1q = *(const float4*)(hcur + 1 * 264 + q * 4);
            float4 h2q = *(const float4*)(hcur + 2 * 264 + q * 4);
            float4 h3q = *(const float4*)(hcur + 3 * 264 + q * 4);
#define RSTEP(K2, C)                                                      \
            {                                                             \
                ulonglong2 wv = *(const ulonglong2*)(wp + q * 16 + K2 * 4); \
                unsigned long long p;                                     \
                p = pack2(h0q.C, h0q.C);                                  \
                ffma2(acc[0][0], wv.x, p); ffma2(acc[1][0], wv.y, p);     \
                p = pack2(h1q.C, h1q.C);                                  \
                ffma2(acc[0][1], wv.x, p); ffma2(acc[1][1], wv.y, p);     \
                p = pack2(h2q.C, h2q.C);                                  \
                ffma2(acc[0][2], wv.x, p); ffma2(acc[1][2], wv.y, p);     \
                p = pack2(h3q.C, h3q.C);                                  \
                ffma2(acc[0][3], wv.x, p); ffma2(acc[1][3], wv.y, p);     \
            }
            RSTEP(0, x) RSTEP(1, y) RSTEP(2, z) RSTEP(3, w)
#undef RSTEP
        }
        // store partials: ZP[j][kc][b] (pitch 68 per j)
#pragma unroll
        for (int g2 = 0; g2 < 2; g2++) {
            float l0, h0_, l1, h1_, l2, h2_, l3, h3_;
            unpack2(acc[g2][0], l0, h0_);
            unpack2(acc[g2][1], l1, h1_);
            unpack2(acc[g2][2], l2, h2_);
            unpack2(acc[g2][3], l3, h3_);
            int j0 = jg * 4 + g2 * 2;
            float4 v0 = {l0, l1, l2, l3};
            float4 v1 = {h0_, h1_, h2_, h3_};
            *(float4*)&ZP[j0 * 68 + kc * 4]       = v0;
            *(float4*)&ZP[(j0 + 1) * 68 + kc * 4] = v1;
        }
        __syncthreads();

        // ---------------- reduce phase ----------------
        float s = zxv;
#pragma unroll
        for (int k2 = 0; k2 < 16; k2++) s += ZP[rj * 68 + k2 * 4 + rb];
        ZF[rj * 5 + rb] = s;
        __syncthreads();

        // ---------------- cell phase ----------------
        if (rj < 32) {
            float iv = ZF[rj * 5 + rb];
            float jv = ZF[(32 + rj) * 5 + rb];
            float ov = ZF[(64 + rj) * 5 + rb];
            float ig = sigm(iv);
            creg = (1.f - ig) * creg + ig * tanhf(jv);
            float nh = tanhf(creg) * sigm(ov);
            int col = (int)rank * 32 + rj;
            unsigned ha = smaddr(&HS[((tt + 1) & 1) * 1056 + rb * 264 + col]);
#pragma unroll
            for (unsigned r2 = 0; r2 < 8; r2++) st_cluster_f32(ha, r2, nh);
            y[((size_t)t * BATCH + bglob) * 512 + dir * 256 + col] = nh;
            if (tt == T_LEN - 1) {
                int si = 2 * layer + dir;
                hn[(size_t)si * (BATCH * 256) + bglob * 256 + col] = nh;
                cn[(size_t)si * (BATCH * 256) + bglob * 256 + col] = creg;
            }
        }
        CLUSTER_SYNC();
    }
}

// ------------------------- highway elementwise -----------------------------
__global__ __launch_bounds__(256) void highway_ew(
    const float4* __restrict__ gz, const float4* __restrict__ raw,
    const float4* __restrict__ prev, float4* __restrict__ dst, int n4)
{
    int i = blockIdx.x * blockDim.x + threadIdx.x;
    if (i < n4) {
        float4 G = gz[i], R = raw[i], P = prev[i], o;
        float s;
        s = sigm(G.x); o.x = s * R.x + (1.f - s) * P.x;
        s = sigm(G.y); o.y = s * R.y + (1.f - s) * P.y;
        s = sigm(G.z); o.z = s * R.z + (1.f - s) * P.z;
        s = sigm(G.w); o.w = s * R.w + (1.f - s) * P.w;
        dst[i] = o;
    }
}

// ------------------------- host launcher -----------------------------------
extern "C" void kernel_launch(void* const* d_in, const int* in_sizes, int n_in,
                              void* d_out, int out_size)
{
    (void)in_sizes; (void)n_in; (void)out_size;

    const float* x    = (const float*)d_in[0];
    const float* h0   = (const float*)d_in[1];
    const float* c0   = (const float*)d_in[2];
    const float* Wf0  = (const float*)d_in[3];
    const float* bf0  = (const float*)d_in[4];
    const float* Wb0  = (const float*)d_in[5];
    const float* bb0  = (const float*)d_in[6];
    const float* Wf1  = (const float*)d_in[7];
    const float* bf1  = (const float*)d_in[8];
    const float* Wb1  = (const float*)d_in[9];
    const float* bb1  = (const float*)d_in[10];
    const float* Wf2  = (const float*)d_in[11];
    const float* bf2  = (const float*)d_in[12];
    const float* Wb2  = (const float*)d_in[13];
    const float* bb2  = (const float*)d_in[14];
    const float* W_hw = (const float*)d_in[15];
    const float* b_hw = (const float*)d_in[16];

    float* out = (float*)d_out;
    float* hn  = out + (size_t)MROWS * 512;
    float* cn  = hn + 6 * BATCH * 256;

    float *zxf, *zxb, *buf0, *buf1;
    cudaGetSymbolAddress((void**)&zxf,  g_zxf);
    cudaGetSymbolAddress((void**)&zxb,  g_zxb);
    cudaGetSymbolAddress((void**)&buf0, g_buf0);
    cudaGetSymbolAddress((void**)&buf1, g_buf1);

    static int attr_done = 0;
    if (!attr_done) {
        cudaFuncSetAttribute(recur2, cudaFuncAttributeMaxDynamicSharedMemorySize, RC_BYTES);
        attr_done = 1;
    }

    const dim3 g768(ZN / BN, MROWS / BM);
    const dim3 g512(512 / BN, MROWS / BM);
    const int n4 = (MROWS * 512) / 4;
    const int ewb = (n4 + 255) / 256;

    // ---- layer 0 ----
    sgemm_bias<<<g768, 256>>>(x, Wf0, bf0, zxf, MROWS, ZN, 256);
    sgemm_bias<<<g768, 256>>>(x, Wb0, bb0, zxb, MROWS, ZN, 256);
    recur2<<<128, 384, RC_BYTES>>>(Wf0 + (size_t)256 * ZN, Wb0 + (size_t)256 * ZN,
                                   h0, c0, buf0, hn, cn, 0);
    // ---- layer 1 ----
    sgemm_bias<<<g768, 256>>>(buf0, Wf1, bf1, zxf, MROWS, ZN, 512);
    sgemm_bias<<<g768, 256>>>(buf0, Wb1, bb1, zxb, MROWS, ZN, 512);
    recur2<<<128, 384, RC_BYTES>>>(Wf1 + (size_t)512 * ZN, Wb1 + (size_t)512 * ZN,
                                   h0, c0, buf1, hn, cn, 1);
    sgemm_bias<<<g512, 256>>>(buf1, W_hw, b_hw, zxf, MROWS, 512, 512);
    highway_ew<<<ewb, 256>>>((const float4*)zxf, (const float4*)buf1,
                             (const float4*)buf0, (float4*)buf1, n4);
    // ---- layer 2 ----
    sgemm_bias<<<g768, 256>>>(buf1, Wf2, bf2, zxf, MROWS, ZN, 512);
    sgemm_bias<<<g768, 256>>>(buf1, Wb2, bb2, zxb, MROWS, ZN, 512);
    recur2<<<128, 384, RC_BYTES>>>(Wf2 + (size_t)512 * ZN, Wb2 + (size_t)512 * ZN,
                                   h0, c0, buf0, hn, cn, 2);
    sgemm_bias<<<g512, 256>>>(buf0, W_hw, b_hw, zxf, MROWS, 512, 512);
    highway_ew<<<ewb, 256>>>((const float4*)zxf, (const float4*)buf0,
                             (const float4*)buf1, (float4*)out, n4);
}

// round 3
// speedup vs baseline: 1.6360x; 1.1186x over previous
#include <cuda_runtime.h>
#include <cstdint>
#include <cstddef>

// ---------------------------------------------------------------------------
// BiLSTM T=1024 B=32 H=256 L=3, 3-gate cell, highway on l>0.
//   zx GEMMs: FFMA2 SGEMM, 2-stage double-buffered pipeline.
//   recurrence: 16 clusters x 8 CTAs (dir x 4-batch group). Wh slice lives in
//   REGISTERS (64/thread); h exchanged via DSMEM; one cluster barrier/step.
// ---------------------------------------------------------------------------

#define T_LEN 1024
#define BATCH 32
#define ZN    768
#define MROWS (T_LEN*BATCH)

__device__ float g_zxf[(size_t)MROWS * ZN];
__device__ float g_zxb[(size_t)MROWS * ZN];
__device__ float g_buf0[(size_t)MROWS * 512];
__device__ float g_buf1[(size_t)MROWS * 512];

__device__ __forceinline__ float sigm(float x) { return 1.f / (1.f + __expf(-x)); }

__device__ __forceinline__ unsigned long long pack2(float lo, float hi) {
    unsigned long long r;
    asm("mov.b64 %0, {%1, %2};" : "=l"(r) : "f"(lo), "f"(hi));
    return r;
}
__device__ __forceinline__ void unpack2(unsigned long long v, float& lo, float& hi) {
    asm("mov.b64 {%0, %1}, %2;" : "=f"(lo), "=f"(hi) : "l"(v));
}
__device__ __forceinline__ void ffma2(unsigned long long& d, unsigned long long a, unsigned long long b) {
    asm("fma.rn.f32x2 %0, %1, %2, %3;" : "=l"(d) : "l"(a), "l"(b), "l"(d));
}
__device__ __forceinline__ unsigned smaddr(const void* p) {
    unsigned a;
    asm("{ .reg .u64 t; cvta.to.shared.u64 t, %1; cvt.u32.u64 %0, t; }" : "=r"(a) : "l"(p));
    return a;
}
__device__ __forceinline__ void st_cluster_f32(unsigned addr, unsigned rank, float v) {
    asm volatile("{ .reg .b32 ra; mapa.shared::cluster.u32 ra, %0, %1; st.shared::cluster.f32 [ra], %2; }"
                 :: "r"(addr), "r"(rank), "f"(v) : "memory");
}
#define CLUSTER_SYNC() do { \
    asm volatile("barrier.cluster.arrive.aligned;" ::: "memory"); \
    asm volatile("barrier.cluster.wait.aligned;" ::: "memory"); \
} while (0)

// ------------------------- SGEMM (FFMA2, 2-stage pipeline) -----------------
#define BM 128
#define BN 64
#define BK 16

__global__ __launch_bounds__(256) void sgemm_bias(
    const float* __restrict__ A, const float* __restrict__ B,
    const float* __restrict__ bias, float* __restrict__ C,
    int M, int N, int K)
{
    __shared__ float As[2][BK][BM];
    __shared__ float Bs[2][BK][BN];

    const int bm = blockIdx.y * BM;
    const int bn = blockIdx.x * BN;
    const int tid = threadIdx.x;
    const int tx = tid & 15;
    const int ty = tid >> 4;

    const int ar0 = tid >> 2;            // A rows this thread loads
    const int ac4 = tid & 3;             // k-group
    const int brow = tid >> 4;           // B row
    const int bc4 = tid & 15;

    unsigned long long acc2[4][4];
#pragma unroll
    for (int p = 0; p < 4; p++)
#pragma unroll
        for (int j = 0; j < 4; j++) acc2[p][j] = 0ull;

    const int nIter = K >> 4;

    float4 a0, a1, b0;
    a0 = *(const float4*)(A + (size_t)(bm + ar0) * K + ac4 * 4);
    a1 = *(const float4*)(A + (size_t)(bm + 64 + ar0) * K + ac4 * 4);
    b0 = *(const float4*)(B + (size_t)brow * N + bn + bc4 * 4);

    for (int it = 0; it < nIter; it++) {
        const int s = it & 1;
        // STS (A transposed)
        As[s][ac4 * 4 + 0][ar0] = a0.x;
        As[s][ac4 * 4 + 1][ar0] = a0.y;
        As[s][ac4 * 4 + 2][ar0] = a0.z;
        As[s][ac4 * 4 + 3][ar0] = a0.w;
        As[s][ac4 * 4 + 0][64 + ar0] = a1.x;
        As[s][ac4 * 4 + 1][64 + ar0] = a1.y;
        As[s][ac4 * 4 + 2][64 + ar0] = a1.z;
        As[s][ac4 * 4 + 3][64 + ar0] = a1.w;
        *(float4*)&Bs[s][brow][bc4 * 4] = b0;
        __syncthreads();
        if (it + 1 < nIter) {
            int k0 = (it + 1) * BK;
            a0 = *(const float4*)(A + (size_t)(bm + ar0) * K + k0 + ac4 * 4);
            a1 = *(const float4*)(A + (size_t)(bm + 64 + ar0) * K + k0 + ac4 * 4);
            b0 = *(const float4*)(B + (size_t)(k0 + brow) * N + bn + bc4 * 4);
        }
#pragma unroll
        for (int k = 0; k < BK; k++) {
            ulonglong2 A0 = *(const ulonglong2*)&As[s][k][ty * 8];
            ulonglong2 A1 = *(const ulonglong2*)&As[s][k][ty * 8 + 4];
            float4 bv = *(const float4*)&Bs[s][k][tx * 4];
            unsigned long long bb0 = pack2(bv.x, bv.x);
            unsigned long long bb1 = pack2(bv.y, bv.y);
            unsigned long long bb2 = pack2(bv.z, bv.z);
            unsigned long long bb3 = pack2(bv.w, bv.w);
            ffma2(acc2[0][0], A0.x, bb0); ffma2(acc2[1][0], A0.y, bb0);
            ffma2(acc2[2][0], A1.x, bb0); ffma2(acc2[3][0], A1.y, bb0);
            ffma2(acc2[0][1], A0.x, bb1); ffma2(acc2[1][1], A0.y, bb1);
            ffma2(acc2[2][1], A1.x, bb1); ffma2(acc2[3][1], A1.y, bb1);
            ffma2(acc2[0][2], A0.x, bb2); ffma2(acc2[1][2], A0.y, bb2);
            ffma2(acc2[2][2], A1.x, bb2); ffma2(acc2[3][2], A1.y, bb2);
            ffma2(acc2[0][3], A0.x, bb3); ffma2(acc2[1][3], A0.y, bb3);
            ffma2(acc2[2][3], A1.x, bb3); ffma2(acc2[3][3], A1.y, bb3);
        }
        __syncthreads();
    }
    float4 bb = *(const float4*)(bias + bn + tx * 4);
#pragma unroll
    for (int p = 0; p < 4; p++) {
        float lo[4], hi[4];
#pragma unroll
        for (int j = 0; j < 4; j++) unpack2(acc2[p][j], lo[j], hi[j]);
        int row0 = bm + ty * 8 + 2 * p;
        float4 o0, o1;
        o0.x = lo[0] + bb.x; o0.y = lo[1] + bb.y; o0.z = lo[2] + bb.z; o0.w = lo[3] + bb.w;
        o1.x = hi[0] + bb.x; o1.y = hi[1] + bb.y; o1.z = hi[2] + bb.z; o1.w = hi[3] + bb.w;
        *(float4*)(C + (size_t)row0 * N + bn + tx * 4)       = o0;
        *(float4*)(C + (size_t)(row0 + 1) * N + bn + tx * 4) = o1;
    }
}

// ------------------------- recurrent scan (W in registers) -----------------
// 128 CTAs, cluster 8. cid = blockIdx.x/8; dir = cid>>3; bg = cid&7.
// CTA rank r owns h-cols [r*32, r*32+32) -> 96 z-cols x 4 batches.
// 384 threads. Dot: thread = (jg = tid%24 [j-quad], kc = tid/24 [16-k chunk]).
//   W: 32 ull regs (pairs (j0,j1),(j2,j3) per k).
// Partials: ZP[b][kc][j]  (pitch 104 per kc, 1672 per b) -> conflict-free read.
// Fused reduce+cell on threads 0..127 (m = tid>>2, b = tid&3).
#define ZP_KP 104
#define ZP_BP 1672

__global__ void __cluster_dims__(8, 1, 1) __launch_bounds__(384, 1)
recur3(const float* __restrict__ Whf, const float* __restrict__ Whb,
       const float* __restrict__ h0, const float* __restrict__ c0,
       float* __restrict__ y, float* __restrict__ hn, float* __restrict__ cn,
       int layer)
{
    __shared__ float HS[2][4 * 264];     // h pingpong, [b][k] pitch 264
    __shared__ float ZP[4 * ZP_BP];      // partials
    __shared__ float ZX[96 * 5];         // prefetched zx

    const int cid = blockIdx.x >> 3;
    const int dir = cid >> 3;
    const int bg  = cid & 7;
    unsigned rank;
    asm("mov.u32 %0, %%cluster_ctarank;" : "=r"(rank));

    const float* Wh = dir ? Whb : Whf;
    const float* zx = dir ? g_zxb : g_zxf;
    const int tid = threadIdx.x;

    const int jg = tid % 24;
    const int kc = tid / 24;
    const int rj = tid >> 2;           // z-col for zx prefetch, 0..95
    const int rb = tid & 3;
    const int bglob_r = bg * 4 + rb;
    const int zcolr = (rj >> 5) * 256 + (int)rank * 32 + (rj & 31);

    // ---- W slice into registers: 16 k x (2 j-pairs) ----
    const int gate = jg >> 3;                        // 0..2
    const int colb = (int)rank * 32 + (jg & 7) * 4;  // j0 column
    const int zc0 = gate * 256 + colb;
    unsigned long long wA[16], wB[16];
#pragma unroll
    for (int kl = 0; kl < 16; kl++) {
        const float* wrow = Wh + (size_t)(kc * 16 + kl) * ZN + zc0;
        wA[kl] = pack2(__ldg(wrow + 0), __ldg(wrow + 1));
        wB[kl] = pack2(__ldg(wrow + 2), __ldg(wrow + 3));
    }

    // ---- init h (buffer 0) and c ----
    for (int it = tid; it < 4 * 256; it += 384) {
        int b = it >> 8, k = it & 255;
        HS[0][b * 264 + k] = h0[k];
    }
    float creg = 0.f;
    {
        int m = tid >> 2;
        if (tid < 128) creg = c0[(int)rank * 32 + m];
    }
    __syncthreads();
    CLUSTER_SYNC();

    const int t0 = dir ? (T_LEN - 1) : 0;
    float zxv = __ldg(&zx[((size_t)t0 * BATCH + bglob_r) * ZN + zcolr]);

    for (int tt = 0; tt < T_LEN; tt++) {
        const int t = dir ? (T_LEN - 1 - tt) : tt;

        // stash this step's zx; prefetch next step's
        ZX[rj * 5 + rb] = zxv;
        if (tt + 1 < T_LEN) {
            const int tn = dir ? (t - 1) : (t + 1);
            zxv = __ldg(&zx[((size_t)tn * BATCH + bglob_r) * ZN + zcolr]);
        }

        // ---------------- dot (W in regs, h broadcast from SMEM) ----------
        const float* hc = &HS[tt & 1][kc * 16];
        unsigned long long acc[2][4];
#pragma unroll
        for (int g2 = 0; g2 < 2; g2++)
#pragma unroll
            for (int b = 0; b < 4; b++) acc[g2][b] = 0ull;

#pragma unroll
        for (int q = 0; q < 4; q++) {
            float4 h0q = *(const float4*)(hc + 0 * 264 + q * 4);
            float4 h1q = *(const float4*)(hc + 1 * 264 + q * 4);
            float4 h2q = *(const float4*)(hc + 2 * 264 + q * 4);
            float4 h3q = *(const float4*)(hc + 3 * 264 + q * 4);
#define RSTEP(C, KL)                                                   \
            {                                                          \
                unsigned long long p;                                  \
                p = pack2(h0q.C, h0q.C);                               \
                ffma2(acc[0][0], wA[KL], p); ffma2(acc[1][0], wB[KL], p); \
                p = pack2(h1q.C, h1q.C);                               \
                ffma2(acc[0][1], wA[KL], p); ffma2(acc[1][1], wB[KL], p); \
                p = pack2(h2q.C, h2q.C);                               \
                ffma2(acc[0][2], wA[KL], p); ffma2(acc[1][2], wB[KL], p); \
                p = pack2(h3q.C, h3q.C);                               \
                ffma2(acc[0][3], wA[KL], p); ffma2(acc[1][3], wB[KL], p); \
            }
            RSTEP(x, (q * 4 + 0)) RSTEP(y, (q * 4 + 1))
            RSTEP(z, (q * 4 + 2)) RSTEP(w, (q * 4 + 3))
#undef RSTEP
        }
        // partial store: one ST.128 per b -> (j0..j3)
#pragma unroll
        for (int b = 0; b < 4; b++) {
            ulonglong2 v;
            v.x = acc[0][b];
            v.y = acc[1][b];
            *(ulonglong2*)&ZP[b * ZP_BP + kc * ZP_KP + jg * 4] = v;
        }
        __syncthreads();

        // ---------------- fused reduce + cell ----------------
        if (tid < 128) {
            const int m = tid >> 2;
            const int b = tid & 3;
            float sg[3];
#pragma unroll
            for (int g = 0; g < 3; g++) {
                const int j = g * 32 + m;
                float s = ZX[j * 5 + b];
                const float* zp = &ZP[b * ZP_BP + j];
#pragma unroll
                for (int k2 = 0; k2 < 16; k2++) s += zp[k2 * ZP_KP];
                sg[g] = s;
            }
            float ig = sigm(sg[0]);
            creg = (1.f - ig) * creg + ig * tanhf(sg[1]);
            float nh = tanhf(creg) * sigm(sg[2]);

            const int col = (int)rank * 32 + m;
            const int bglob = bg * 4 + b;
            unsigned ha = smaddr(&HS[(tt + 1) & 1][b * 264 + col]);
#pragma unroll
            for (unsigned r2 = 0; r2 < 8; r2++) st_cluster_f32(ha, r2, nh);
            y[((size_t)t * BATCH + bglob) * 512 + dir * 256 + col] = nh;
            if (tt == T_LEN - 1) {
                int si = 2 * layer + dir;
                hn[(size_t)si * (BATCH * 256) + bglob * 256 + col] = nh;
                cn[(size_t)si * (BATCH * 256) + bglob * 256 + col] = creg;
            }
        }
        CLUSTER_SYNC();
    }
}

// ------------------------- highway elementwise -----------------------------
__global__ __launch_bounds__(256) void highway_ew(
    const float4* __restrict__ gz, const float4* __restrict__ raw,
    const float4* __restrict__ prev, float4* __restrict__ dst, int n4)
{
    int i = blockIdx.x * blockDim.x + threadIdx.x;
    if (i < n4) {
        float4 G = gz[i], R = raw[i], P = prev[i], o;
        float s;
        s = sigm(G.x); o.x = s * R.x + (1.f - s) * P.x;
        s = sigm(G.y); o.y = s * R.y + (1.f - s) * P.y;
        s = sigm(G.z); o.z = s * R.z + (1.f - s) * P.z;
        s = sigm(G.w); o.w = s * R.w + (1.f - s) * P.w;
        dst[i] = o;
    }
}

// ------------------------- host launcher -----------------------------------
extern "C" void kernel_launch(void* const* d_in, const int* in_sizes, int n_in,
                              void* d_out, int out_size)
{
    (void)in_sizes; (void)n_in; (void)out_size;

    const float* x    = (const float*)d_in[0];
    const float* h0   = (const float*)d_in[1];
    const float* c0   = (const float*)d_in[2];
    const float* Wf0  = (const float*)d_in[3];
    const float* bf0  = (const float*)d_in[4];
    const float* Wb0  = (const float*)d_in[5];
    const float* bb0  = (const float*)d_in[6];
    const float* Wf1  = (const float*)d_in[7];
    const float* bf1  = (const float*)d_in[8];
    const float* Wb1  = (const float*)d_in[9];
    const float* bb1  = (const float*)d_in[10];
    const float* Wf2  = (const float*)d_in[11];
    const float* bf2  = (const float*)d_in[12];
    const float* Wb2  = (const float*)d_in[13];
    const float* bb2  = (const float*)d_in[14];
    const float* W_hw = (const float*)d_in[15];
    const float* b_hw = (const float*)d_in[16];

    float* out = (float*)d_out;
    float* hn  = out + (size_t)MROWS * 512;
    float* cn  = hn + 6 * BATCH * 256;

    float *zxf, *zxb, *buf0, *buf1;
    cudaGetSymbolAddress((void**)&zxf,  g_zxf);
    cudaGetSymbolAddress((void**)&zxb,  g_zxb);
    cudaGetSymbolAddress((void**)&buf0, g_buf0);
    cudaGetSymbolAddress((void**)&buf1, g_buf1);

    const dim3 g768(ZN / BN, MROWS / BM);
    const dim3 g512(512 / BN, MROWS / BM);
    const int n4 = (MROWS * 512) / 4;
    const int ewb = (n4 + 255) / 256;

    // ---- layer 0 ----
    sgemm_bias<<<g768, 256>>>(x, Wf0, bf0, zxf, MROWS, ZN, 256);
    sgemm_bias<<<g768, 256>>>(x, Wb0, bb0, zxb, MROWS, ZN, 256);
    recur3<<<128, 384>>>(Wf0 + (size_t)256 * ZN, Wb0 + (size_t)256 * ZN,
                         h0, c0, buf0, hn, cn, 0);
    // ---- layer 1 ----
    sgemm_bias<<<g768, 256>>>(buf0, Wf1, bf1, zxf, MROWS, ZN, 512);
    sgemm_bias<<<g768, 256>>>(buf0, Wb1, bb1, zxb, MROWS, ZN, 512);
    recur3<<<128, 384>>>(Wf1 + (size_t)512 * ZN, Wb1 + (size_t)512 * ZN,
                         h0, c0, buf1, hn, cn, 1);
    sgemm_bias<<<g512, 256>>>(buf1, W_hw, b_hw, zxf, MROWS, 512, 512);
    highway_ew<<<ewb, 256>>>((const float4*)zxf, (const float4*)buf1,
                             (const float4*)buf0, (float4*)buf1, n4);
    // ---- layer 2 ----
    sgemm_bias<<<g768, 256>>>(buf1, Wf2, bf2, zxf, MROWS, ZN, 512);
    sgemm_bias<<<g768, 256>>>(buf1, Wb2, bb2, zxb, MROWS, ZN, 512);
    recur3<<<128, 384>>>(Wf2 + (size_t)512 * ZN, Wb2 + (size_t)512 * ZN,
                         h0, c0, buf0, hn, cn, 2);
    sgemm_bias<<<g512, 256>>>(buf0, W_hw, b_hw, zxf, MROWS, 512, 512);
    highway_ew<<<ewb, 256>>>((const float4*)zxf, (const float4*)buf0,
                             (const float4*)buf1, (float4*)out, n4);
}

// round 5
// speedup vs baseline: 1.7232x; 1.0533x over previous
#include <cuda_runtime.h>
#include <cstdint>
#include <cstddef>

// ---------------------------------------------------------------------------
// BiLSTM T=1024 B=32 H=256 L=3, 3-gate cell, highway on l>0.
//   zx GEMMs: FFMA2 SGEMM, 2-stage double-buffered pipeline.
//   recurrence: 16 clusters x 8 CTAs (dir x 4-batch group). Wh in registers;
//   h exchanged via vectorized DSMEM stores; per-CTA mbarrier (count 8)
//   producer/consumer sync using documented PTX forms only.
// ---------------------------------------------------------------------------

#define T_LEN 1024
#define BATCH 32
#define ZN    768
#define MROWS (T_LEN*BATCH)

__device__ float g_zxf[(size_t)MROWS * ZN];
__device__ float g_zxb[(size_t)MROWS * ZN];
__device__ float g_buf0[(size_t)MROWS * 512];
__device__ float g_buf1[(size_t)MROWS * 512];

__device__ __forceinline__ float sigm(float x) { return 1.f / (1.f + __expf(-x)); }

__device__ __forceinline__ unsigned long long pack2(float lo, float hi) {
    unsigned long long r;
    asm("mov.b64 %0, {%1, %2};" : "=l"(r) : "f"(lo), "f"(hi));
    return r;
}
__device__ __forceinline__ void unpack2(unsigned long long v, float& lo, float& hi) {
    asm("mov.b64 {%0, %1}, %2;" : "=f"(lo), "=f"(hi) : "l"(v));
}
__device__ __forceinline__ void ffma2(unsigned long long& d, unsigned long long a, unsigned long long b) {
    asm("fma.rn.f32x2 %0, %1, %2, %3;" : "=l"(d) : "l"(a), "l"(b), "l"(d));
}
__device__ __forceinline__ unsigned smaddr(const void* p) {
    unsigned a;
    asm("{ .reg .u64 t; cvta.to.shared.u64 t, %1; cvt.u32.u64 %0, t; }" : "=r"(a) : "l"(p));
    return a;
}
__device__ __forceinline__ void st_cluster_f128(unsigned addr, unsigned rank, float4 v) {
    asm volatile("{ .reg .b32 ra; mapa.shared::cluster.u32 ra, %0, %1; "
                 "st.shared::cluster.v4.f32 [ra], {%2,%3,%4,%5}; }"
                 :: "r"(addr), "r"(rank), "f"(v.x), "f"(v.y), "f"(v.z), "f"(v.w) : "memory");
}
__device__ __forceinline__ void mbar_init(unsigned addr, unsigned cnt) {
    asm volatile("mbarrier.init.shared.b64 [%0], %1;" :: "r"(addr), "r"(cnt) : "memory");
}
// Documented remote arrive (ptx_helpers MBARRIER_ARRIVE_CLUSTER form).
__device__ __forceinline__ void mbar_arrive_remote(unsigned addr, unsigned rank) {
    asm volatile("{ .reg .b32 ra; mapa.shared::cluster.u32 ra, %0, %1; "
                 "mbarrier.arrive.shared::cluster.b64 _, [ra]; }"
                 :: "r"(addr), "r"(rank) : "memory");
}
__device__ __forceinline__ void fence_cluster() {
    asm volatile("fence.acq_rel.cluster;" ::: "memory");
}
// Documented wait (ptx_helpers MBARRIER_WAIT_PARITY form, acquire.cta).
__device__ __forceinline__ void mbar_wait(unsigned addr, unsigned parity) {
    unsigned done;
    asm volatile("{ .reg .pred p; "
                 "mbarrier.try_wait.parity.acquire.cta.shared::cta.b64 p, [%1], %2; "
                 "selp.b32 %0, 1, 0, p; }"
                 : "=r"(done) : "r"(addr), "r"(parity) : "memory");
    if (!done) {
        asm volatile("{ .reg .pred P1; "
                     "WL_%=: mbarrier.try_wait.parity.acquire.cta.shared::cta.b64 P1, [%0], %1, 0x989680; "
                     "@P1 bra.uni WD_%=; bra.uni WL_%=; WD_%=: }"
                     :: "r"(addr), "r"(parity) : "memory");
    }
}
#define CLUSTER_SYNC() do { \
    asm volatile("barrier.cluster.arrive.aligned;" ::: "memory"); \
    asm volatile("barrier.cluster.wait.aligned;" ::: "memory"); \
} while (0)

// ------------------------- SGEMM (FFMA2, 2-stage pipeline) -----------------
#define BM 128
#define BN 64
#define BK 16

__global__ __launch_bounds__(256) void sgemm_bias(
    const float* __restrict__ A, const float* __restrict__ B,
    const float* __restrict__ bias, float* __restrict__ C,
    int M, int N, int K)
{
    __shared__ float As[2][BK][BM];
    __shared__ float Bs[2][BK][BN];

    const int bm = blockIdx.y * BM;
    const int bn = blockIdx.x * BN;
    const int tid = threadIdx.x;
    const int tx = tid & 15;
    const int ty = tid >> 4;

    const int ar0 = tid >> 2;
    const int ac4 = tid & 3;
    const int brow = tid >> 4;
    const int bc4 = tid & 15;

    unsigned long long acc2[4][4];
#pragma unroll
    for (int p = 0; p < 4; p++)
#pragma unroll
        for (int j = 0; j < 4; j++) acc2[p][j] = 0ull;

    const int nIter = K >> 4;

    float4 a0, a1, b0;
    a0 = *(const float4*)(A + (size_t)(bm + ar0) * K + ac4 * 4);
    a1 = *(const float4*)(A + (size_t)(bm + 64 + ar0) * K + ac4 * 4);
    b0 = *(const float4*)(B + (size_t)brow * N + bn + bc4 * 4);

    for (int it = 0; it < nIter; it++) {
        const int s = it & 1;
        As[s][ac4 * 4 + 0][ar0] = a0.x;
        As[s][ac4 * 4 + 1][ar0] = a0.y;
        As[s][ac4 * 4 + 2][ar0] = a0.z;
        As[s][ac4 * 4 + 3][ar0] = a0.w;
        As[s][ac4 * 4 + 0][64 + ar0] = a1.x;
        As[s][ac4 * 4 + 1][64 + ar0] = a1.y;
        As[s][ac4 * 4 + 2][64 + ar0] = a1.z;
        As[s][ac4 * 4 + 3][64 + ar0] = a1.w;
        *(float4*)&Bs[s][brow][bc4 * 4] = b0;
        __syncthreads();
        if (it + 1 < nIter) {
            int k0 = (it + 1) * BK;
            a0 = *(const float4*)(A + (size_t)(bm + ar0) * K + k0 + ac4 * 4);
            a1 = *(const float4*)(A + (size_t)(bm + 64 + ar0) * K + k0 + ac4 * 4);
            b0 = *(const float4*)(B + (size_t)(k0 + brow) * N + bn + bc4 * 4);
        }
#pragma unroll
        for (int k = 0; k < BK; k++) {
            ulonglong2 A0 = *(const ulonglong2*)&As[s][k][ty * 8];
            ulonglong2 A1 = *(const ulonglong2*)&As[s][k][ty * 8 + 4];
            float4 bv = *(const float4*)&Bs[s][k][tx * 4];
            unsigned long long bb0 = pack2(bv.x, bv.x);
            unsigned long long bb1 = pack2(bv.y, bv.y);
            unsigned long long bb2 = pack2(bv.z, bv.z);
            unsigned long long bb3 = pack2(bv.w, bv.w);
            ffma2(acc2[0][0], A0.x, bb0); ffma2(acc2[1][0], A0.y, bb0);
            ffma2(acc2[2][0], A1.x, bb0); ffma2(acc2[3][0], A1.y, bb0);
            ffma2(acc2[0][1], A0.x, bb1); ffma2(acc2[1][1], A0.y, bb1);
            ffma2(acc2[2][1], A1.x, bb1); ffma2(acc2[3][1], A1.y, bb1);
            ffma2(acc2[0][2], A0.x, bb2); ffma2(acc2[1][2], A0.y, bb2);
            ffma2(acc2[2][2], A1.x, bb2); ffma2(acc2[3][2], A1.y, bb2);
            ffma2(acc2[0][3], A0.x, bb3); ffma2(acc2[1][3], A0.y, bb3);
            ffma2(acc2[2][3], A1.x, bb3); ffma2(acc2[3][3], A1.y, bb3);
        }
        __syncthreads();
    }
    float4 bb = *(const float4*)(bias + bn + tx * 4);
#pragma unroll
    for (int p = 0; p < 4; p++) {
        float lo[4], hi[4];
#pragma unroll
        for (int j = 0; j < 4; j++) unpack2(acc2[p][j], lo[j], hi[j]);
        int row0 = bm + ty * 8 + 2 * p;
        float4 o0, o1;
        o0.x = lo[0] + bb.x; o0.y = lo[1] + bb.y; o0.z = lo[2] + bb.z; o0.w = lo[3] + bb.w;
        o1.x = hi[0] + bb.x; o1.y = hi[1] + bb.y; o1.z = hi[2] + bb.z; o1.w = hi[3] + bb.w;
        *(float4*)(C + (size_t)row0 * N + bn + tx * 4)       = o0;
        *(float4*)(C + (size_t)(row0 + 1) * N + bn + tx * 4) = o1;
    }
}

// ------------------------- recurrent scan ----------------------------------
// 128 CTAs, cluster 8. cid = blockIdx.x/8; dir = cid>>3; bg = cid&7.
// CTA rank r owns h-cols [r*32, r*32+32) -> 96 z-cols x 4 batches. 384 thr.
// Dot: (jg = tid%24, kc = tid/24), W in regs (32 ull).
// Partials ZP[b][kc][j] (pitch 104/kc, 1672/b). Reduce: all 384 threads.
// Cell on 128 threads; h pushed via st.shared::cluster.v4 (8 lanes/warp);
// sync = per-CTA mbarrier (count 8), remote release-arrives by thread 0.
// Safety of 1 barrier/step: a CTA arrives only after its reads of the old
// h buffer, and the wait at the top of each step bounds skew to 1 step, so
// writes always target a buffer nobody reads anymore.
#define ZP_KP 104
#define ZP_BP 1672

__global__ void __cluster_dims__(8, 1, 1) __launch_bounds__(384, 1)
recur5(const float* __restrict__ Whf, const float* __restrict__ Whb,
       const float* __restrict__ h0, const float* __restrict__ c0,
       float* __restrict__ y, float* __restrict__ hn, float* __restrict__ cn,
       int layer)
{
    __shared__ float HS[2][4 * 264];     // h pingpong, [b][k] pitch 264
    __shared__ float ZP[4 * ZP_BP];      // dot partials
    __shared__ float ZX[96 * 4];         // current-step zx
    __shared__ float ZF[96 * 4];         // reduced gate sums
    __shared__ float SH[4 * 40];         // nh staging for vector pushes
    __shared__ unsigned long long hmb;   // arrival mbarrier (count 8)

    const int cid = blockIdx.x >> 3;
    const int dir = cid >> 3;
    const int bg  = cid & 7;
    unsigned rank;
    asm("mov.u32 %0, %%cluster_ctarank;" : "=r"(rank));

    const float* Wh = dir ? Whb : Whf;
    const float* zx = dir ? g_zxb : g_zxf;
    const int tid = threadIdx.x;
    const unsigned hmb_a = smaddr(&hmb);

    const int jg = tid % 24;
    const int kc = tid / 24;
    const int rj = tid >> 2;
    const int rb = tid & 3;
    const int bglob_r = bg * 4 + rb;
    const int zcolr = (rj >> 5) * 256 + (int)rank * 32 + (rj & 31);

    // ---- W slice into registers ----
    const int gate = jg >> 3;
    const int colb = (int)rank * 32 + (jg & 7) * 4;
    const int zc0 = gate * 256 + colb;
    unsigned long long wA[16], wB[16];
#pragma unroll
    for (int kl = 0; kl < 16; kl++) {
        const float* wrow = Wh + (size_t)(kc * 16 + kl) * ZN + zc0;
        wA[kl] = pack2(__ldg(wrow + 0), __ldg(wrow + 1));
        wB[kl] = pack2(__ldg(wrow + 2), __ldg(wrow + 3));
    }

    // ---- init h buffer 0, c, mbarrier ----
    for (int it = tid; it < 4 * 256; it += 384) {
        int b = it >> 8, k = it & 255;
        HS[0][b * 264 + k] = h0[k];
    }
    float creg = 0.f;
    if (tid < 128) creg = c0[(int)rank * 32 + (tid >> 2)];
    if (tid == 0) mbar_init(hmb_a, 8);
    __syncthreads();
    CLUSTER_SYNC();   // inits + HS[0] visible cluster-wide before any arrive

    const int t0 = dir ? (T_LEN - 1) : 0;
    float zxv = __ldg(&zx[((size_t)t0 * BATCH + bglob_r) * ZN + zcolr]);

    for (int tt = 0; tt < T_LEN; tt++) {
        const int t = dir ? (T_LEN - 1 - tt) : tt;

        if (tt) mbar_wait(hmb_a, (tt & 1) ^ 1);   // h[tt&1] ready

        ZX[rj * 4 + rb] = zxv;
        if (tt + 1 < T_LEN) {
            const int tn = dir ? (t - 1) : (t + 1);
            zxv = __ldg(&zx[((size_t)tn * BATCH + bglob_r) * ZN + zcolr]);
        }

        // ---------------- dot (W in regs, h broadcast from SMEM) ----------
        const float* hc = &HS[tt & 1][kc * 16];
        unsigned long long acc[2][4];
#pragma unroll
        for (int g2 = 0; g2 < 2; g2++)
#pragma unroll
            for (int b = 0; b < 4; b++) acc[g2][b] = 0ull;

#pragma unroll
        for (int q = 0; q < 4; q++) {
            float4 h0q = *(const float4*)(hc + 0 * 264 + q * 4);
            float4 h1q = *(const float4*)(hc + 1 * 264 + q * 4);
            float4 h2q = *(const float4*)(hc + 2 * 264 + q * 4);
            float4 h3q = *(const float4*)(hc + 3 * 264 + q * 4);
#define RSTEP(C, KL)                                                   \
            {                                                          \
                unsigned long long p;                                  \
                p = pack2(h0q.C, h0q.C);                               \
                ffma2(acc[0][0], wA[KL], p); ffma2(acc[1][0], wB[KL], p); \
                p = pack2(h1q.C, h1q.C);                               \
                ffma2(acc[0][1], wA[KL], p); ffma2(acc[1][1], wB[KL], p); \
                p = pack2(h2q.C, h2q.C);                               \
                ffma2(acc[0][2], wA[KL], p); ffma2(acc[1][2], wB[KL], p); \
                p = pack2(h3q.C, h3q.C);                               \
                ffma2(acc[0][3], wA[KL], p); ffma2(acc[1][3], wB[KL], p); \
            }
            RSTEP(x, (q * 4 + 0)) RSTEP(y, (q * 4 + 1))
            RSTEP(z, (q * 4 + 2)) RSTEP(w, (q * 4 + 3))
#undef RSTEP
        }
#pragma unroll
        for (int b = 0; b < 4; b++) {
            ulonglong2 v;
            v.x = acc[0][b];
            v.y = acc[1][b];
            *(ulonglong2*)&ZP[b * ZP_BP + kc * ZP_KP + jg * 4] = v;
        }
        __syncthreads();

        // ---------------- reduce: all 384 threads, one (j,b) each ---------
        {
            float s = ZX[rj * 4 + rb];
            const float* zp = &ZP[rb * ZP_BP + rj];
#pragma unroll
            for (int k2 = 0; k2 < 16; k2++) s += zp[k2 * ZP_KP];
            ZF[rj * 4 + rb] = s;
        }
        __syncthreads();

        // ---------------- cell + vectorized h push ------------------------
        if (tid < 128) {
            const int m = tid >> 2;
            const int b = tid & 3;
            const int w = tid >> 5;
            const int lane = tid & 31;
            float iv = ZF[m * 4 + b];
            float jv = ZF[(32 + m) * 4 + b];
            float ov = ZF[(64 + m) * 4 + b];
            float ig = sigm(iv);
            creg = (1.f - ig) * creg + ig * tanhf(jv);
            float nh = tanhf(creg) * sigm(ov);

            SH[b * 40 + m] = nh;
            __syncwarp();
            if ((tt + 1 < T_LEN) && lane < 8) {
                const int pb = lane & 3, half = lane >> 2;
                const int base = w * 8 + half * 4;
                float4 v = *(const float4*)&SH[pb * 40 + base];
                unsigned da = smaddr(&HS[(tt + 1) & 1][pb * 264 + (int)rank * 32 + base]);
#pragma unroll
                for (unsigned r2 = 0; r2 < 8; r2++) st_cluster_f128(da, r2, v);
            }

            const int col = (int)rank * 32 + m;
            const int bglob = bg * 4 + b;
            y[((size_t)t * BATCH + bglob) * 512 + dir * 256 + col] = nh;
            if (tt == T_LEN - 1) {
                int si = 2 * layer + dir;
                hn[(size_t)si * (BATCH * 256) + bglob * 256 + col] = nh;
                cn[(size_t)si * (BATCH * 256) + bglob * 256 + col] = creg;
            }
        }
        if (tt + 1 < T_LEN) {
            __syncthreads();                     // all pushes issued
            if (tid == 0) {
                fence_cluster();                 // cumulativity for peers' stores
#pragma unroll
                for (unsigned r2 = 0; r2 < 8; r2++) mbar_arrive_remote(hmb_a, r2);
            }
        }
    }
}

// ------------------------- highway elementwise -----------------------------
__global__ __launch_bounds__(256) void highway_ew(
    const float4* __restrict__ gz, const float4* __restrict__ raw,
    const float4* __restrict__ prev, float4* __restrict__ dst, int n4)
{
    int i = blockIdx.x * blockDim.x + threadIdx.x;
    if (i < n4) {
        float4 G = gz[i], R = raw[i], P = prev[i], o;
        float s;
        s = sigm(G.x); o.x = s * R.x + (1.f - s) * P.x;
        s = sigm(G.y); o.y = s * R.y + (1.f - s) * P.y;
        s = sigm(G.z); o.z = s * R.z + (1.f - s) * P.z;
        s = sigm(G.w); o.w = s * R.w + (1.f - s) * P.w;
        dst[i] = o;
    }
}

// ------------------------- host launcher -----------------------------------
extern "C" void kernel_launch(void* const* d_in, const int* in_sizes, int n_in,
                              void* d_out, int out_size)
{
    (void)in_sizes; (void)n_in; (void)out_size;

    const float* x    = (const float*)d_in[0];
    const float* h0   = (const float*)d_in[1];
    const float* c0   = (const float*)d_in[2];
    const float* Wf0  = (const float*)d_in[3];
    const float* bf0  = (const float*)d_in[4];
    const float* Wb0  = (const float*)d_in[5];
    const float* bb0  = (const float*)d_in[6];
    const float* Wf1  = (const float*)d_in[7];
    const float* bf1  = (const float*)d_in[8];
    const float* Wb1  = (const float*)d_in[9];
    const float* bb1  = (const float*)d_in[10];
    const float* Wf2  = (const float*)d_in[11];
    const float* bf2  = (const float*)d_in[12];
    const float* Wb2  = (const float*)d_in[13];
    const float* bb2  = (const float*)d_in[14];
    const float* W_hw = (const float*)d_in[15];
    const float* b_hw = (const float*)d_in[16];

    float* out = (float*)d_out;
    float* hn  = out + (size_t)MROWS * 512;
    float* cn  = hn + 6 * BATCH * 256;

    float *zxf, *zxb, *buf0, *buf1;
    cudaGetSymbolAddress((void**)&zxf,  g_zxf);
    cudaGetSymbolAddress((void**)&zxb,  g_zxb);
    cudaGetSymbolAddress((void**)&buf0, g_buf0);
    cudaGetSymbolAddress((void**)&buf1, g_buf1);

    const dim3 g768(ZN / BN, MROWS / BM);
    const dim3 g512(512 / BN, MROWS / BM);
    const int n4 = (MROWS * 512) / 4;
    const int ewb = (n4 + 255) / 256;

    // ---- layer 0 ----
    sgemm_bias<<<g768, 256>>>(x, Wf0, bf0, zxf, MROWS, ZN, 256);
    sgemm_bias<<<g768, 256>>>(x, Wb0, bb0, zxb, MROWS, ZN, 256);
    recur5<<<128, 384>>>(Wf0 + (size_t)256 * ZN, Wb0 + (size_t)256 * ZN,
                         h0, c0, buf0, hn, cn, 0);
    // ---- layer 1 ----
    sgemm_bias<<<g768, 256>>>(buf0, Wf1, bf1, zxf, MROWS, ZN, 512);
    sgemm_bias<<<g768, 256>>>(buf0, Wb1, bb1, zxb, MROWS, ZN, 512);
    recur5<<<128, 384>>>(Wf1 + (size_t)512 * ZN, Wb1 + (size_t)512 * ZN,
                         h0, c0, buf1, hn, cn, 1);
    sgemm_bias<<<g512, 256>>>(buf1, W_hw, b_hw, zxf, MROWS, 512, 512);
    highway_ew<<<ewb, 256>>>((const float4*)zxf, (const float4*)buf1,
                             (const float4*)buf0, (float4*)buf1, n4);
    // ---- layer 2 ----
    sgemm_bias<<<g768, 256>>>(buf1, Wf2, bf2, zxf, MROWS, ZN, 512);
    sgemm_bias<<<g768, 256>>>(buf1, Wb2, bb2, zxb, MROWS, ZN, 512);
    recur5<<<128, 384>>>(Wf2 + (size_t)512 * ZN, Wb2 + (size_t)512 * ZN,
                         h0, c0, buf0, hn, cn, 2);
    sgemm_bias<<<g512, 256>>>(buf0, W_hw, b_hw, zxf, MROWS, 512, 512);
    highway_ew<<<ewb, 256>>>((const float4*)zxf, (const float4*)buf0,
                             (const float4*)buf1, (float4*)out, n4);
}